// round 10
// baseline (speedup 1.0000x reference)
#include <cuda_runtime.h>
#include <cuda_fp16.h>
#include <cstdint>
#include <mma.h>
using namespace nvcuda;

// ---------------- problem constants ----------------
#define BB 2
#define TT 24
#define NN 512
#define DD 512
#define NH 8
#define HD 64
#define MROWS (BB*TT*NN)      // 24576
#define C3 3072               // P row stride: [sQ sK sV tQ tK tV]

// ---------------- scratch (static device globals; no allocation) ----------------
__device__ __half g_Xh [(size_t)MROWS * 1536];
__device__ __half g_Ph [(size_t)MROWS * 3072];
__device__ __half g_Wch[1536 * 3072];
__device__ float  g_bcat[3072];
__device__ __half g_Wgh[1024 * 512];
__device__ __half g_sWoh[512 * 512];
__device__ __half g_tWoh[512 * 512];
__device__ __half g_Wh1h[512 * 512];
__device__ __half g_Wh2h[512 * 512];
__device__ __half g_HSh [(size_t)MROWS * 512];
__device__ __half g_HTh [(size_t)MROWS * 512];
__device__ __half g_HSTh[(size_t)MROWS * 1024];

__device__ __forceinline__ uint2 f4_to_h4(float4 v) {
    __half2 a = __floats2half2_rn(v.x, v.y);
    __half2 b = __floats2half2_rn(v.z, v.w);
    uint2 r;
    r.x = *(unsigned*)&a;
    r.y = *(unsigned*)&b;
    return r;
}

__device__ __forceinline__ void h8_to_f8(uint4 u, float* f) {
    __half2* h = (__half2*)&u;
#pragma unroll
    for (int i = 0; i < 4; i++) {
        float2 t = __half22float2(h[i]);
        f[2 * i] = t.x; f[2 * i + 1] = t.y;
    }
}

#define CP_ASYNC16(dst, src) \
    asm volatile("cp.async.cg.shared.global [%0], [%1], 16;\n" :: "r"(dst), "l"(src))
#define CP_COMMIT() asm volatile("cp.async.commit_group;\n")
#define CP_WAIT(n)  asm volatile("cp.async.wait_group %0;\n" :: "n"(n))

// ---------------- conversion kernels ----------------
__global__ void conv_xc_h(const float* __restrict__ X, const float* __restrict__ STE,
                          __half* __restrict__ Xh)
{
    int idx = blockIdx.x * blockDim.x + threadIdx.x;
    if (idx >= MROWS * 384) return;
    int m = idx / 384, c4 = idx % 384;
    float4 v;
    if (c4 < 128) v = ((const float4*)X)[(size_t)m * 128 + c4];
    else          v = ((const float4*)STE)[(size_t)m * 256 + (c4 - 128)];
    *(uint2*)(Xh + (size_t)idx * 4) = f4_to_h4(v);
}

#define PW_R1 1179648
#define PW_R2 (PW_R1 + 131072)
#define PW_R3 (PW_R2 + 262144)
#define PW_R4 (PW_R3 + 768)
__global__ void prep_weights_k(
    const float* __restrict__ w0, const float* __restrict__ w1,
    const float* __restrict__ w2, const float* __restrict__ w3,
    const float* __restrict__ w4, const float* __restrict__ w5,
    const float* __restrict__ b0, const float* __restrict__ b1,
    const float* __restrict__ b2, const float* __restrict__ b3,
    const float* __restrict__ b4, const float* __restrict__ b5,
    const float* __restrict__ wxs, const float* __restrict__ wxt,
    const float* __restrict__ sWo, const float* __restrict__ tWo,
    const float* __restrict__ wh1, const float* __restrict__ wh2,
    __half* __restrict__ Wch, __half* __restrict__ Wgh,
    __half* __restrict__ sWoh, __half* __restrict__ tWoh,
    __half* __restrict__ Wh1h, __half* __restrict__ Wh2h,
    float* __restrict__ bcat)
{
    int idx = blockIdx.x * blockDim.x + threadIdx.x;
    if (idx < PW_R1) {
        int k = idx / 768, q = idx % 768;
        int j = q >> 7, cq = q & 127;
        const float* ws[6] = {w0, w1, w2, w3, w4, w5};
        float4 v = *(const float4*)(ws[j] + k * 512 + cq * 4);
        *(uint2*)(Wch + (size_t)k * 3072 + j * 512 + cq * 4) = f4_to_h4(v);
    } else if (idx < PW_R2) {
        int e = idx - PW_R1;
        int k = e >> 7, cq = e & 127;
        const float* src = (k < 512) ? (wxs + k * 512) : (wxt + (k - 512) * 512);
        float4 v = *(const float4*)(src + cq * 4);
        *(uint2*)(Wgh + (size_t)k * 512 + cq * 4) = f4_to_h4(v);
    } else if (idx < PW_R3) {
        int e = idx - PW_R2;
        int which = e >> 16, q = e & 65535;
        const float* w = (which == 0) ? sWo : (which == 1) ? tWo : (which == 2) ? wh1 : wh2;
        __half* o = (which == 0) ? sWoh : (which == 1) ? tWoh : (which == 2) ? Wh1h : Wh2h;
        float4 v = *(const float4*)(w + q * 4);
        *(uint2*)(o + (size_t)q * 4) = f4_to_h4(v);
    } else if (idx < PW_R4) {
        int e = idx - PW_R3;
        int j = e >> 7, c = e & 127;
        const float* bs[6] = {b0, b1, b2, b3, b4, b5};
        *(float4*)(bcat + j * 512 + c * 4) = *(const float4*)(bs[j] + c * 4);
    }
}

// ---------------- fp16 tensor GEMM 256x128, BK=32, 3-stage cp.async, 512 thr ----------------
// ACT: 0 bias, 1 bias+relu, 2 bias+residual(float R), 3 gated fusion(half R)
#define G2A_LD 40
#define G2B_LD 136
#define G2AS (256 * G2A_LD)   // 10240 halves / stage
#define G2BS (32 * G2B_LD)    // 4352 halves / stage
#define NST 3
#define G2SMEM (NST * (G2AS + G2BS) * 2)   // 87552 B

template<int ACT, typename OutT>
__global__ void __launch_bounds__(512, 1) gemm2_k(
    const __half* __restrict__ A, const __half* __restrict__ B,
    const float* __restrict__ bias, const void* __restrict__ Rv,
    OutT* __restrict__ C, int K, int lda, int ldb, int ldc, int ldr)
{
    extern __shared__ __align__(16) char dsmem[];
    __half* As = (__half*)dsmem;
    __half* Bs = (__half*)dsmem + NST * G2AS;

    const int tid  = threadIdx.x;
    const int warp = tid >> 5;
    const int lane = tid & 31;
    const int wm   = warp >> 2;   // 0..3 : 64-row subtile
    const int wn   = warp & 3;    // 0..3 : 32-col subtile
    const int m0 = blockIdx.y * 256;
    const int n0 = blockIdx.x * 128;

    const int a_row = tid >> 2;          // 0..127 (two passes cover 256)
    const int a_c8  = (tid & 3) << 3;
    const int b_row = tid >> 4;          // 0..31
    const int b_c8  = (tid & 15) << 3;

    const unsigned int sA = (unsigned int)__cvta_generic_to_shared(As);
    const unsigned int sB = (unsigned int)__cvta_generic_to_shared(Bs);

    const int nk = K >> 5;

    auto issue = [&](int kt, int stage) {
        int k0 = kt << 5;
        CP_ASYNC16(sA + (stage * G2AS + a_row * G2A_LD + a_c8) * 2,
                   A + (size_t)(m0 + a_row) * lda + k0 + a_c8);
        CP_ASYNC16(sA + (stage * G2AS + (128 + a_row) * G2A_LD + a_c8) * 2,
                   A + (size_t)(m0 + 128 + a_row) * lda + k0 + a_c8);
        CP_ASYNC16(sB + (stage * G2BS + b_row * G2B_LD + b_c8) * 2,
                   B + (size_t)(k0 + b_row) * ldb + n0 + b_c8);
    };

    wmma::fragment<wmma::accumulator, 16, 16, 16, float> acc[4][2];
#pragma unroll
    for (int i = 0; i < 4; i++)
#pragma unroll
        for (int j = 0; j < 2; j++) wmma::fill_fragment(acc[i][j], 0.f);

    issue(0, 0); CP_COMMIT();
    if (nk > 1) issue(1, 1);
    CP_COMMIT();

    int buf = 0, nxs = 2;
    for (int kt = 0; kt < nk; kt++) {
        CP_WAIT(1);
        __syncthreads();

        int nx = kt + 2;
        if (nx < nk) issue(nx, nxs);
        CP_COMMIT();
        nxs = (nxs == 2) ? 0 : nxs + 1;

        const __half* Ab = As + buf * G2AS;
        const __half* Bb = Bs + buf * G2BS;
        buf = (buf == 2) ? 0 : buf + 1;
#pragma unroll
        for (int ks = 0; ks < 2; ks++) {
            wmma::fragment<wmma::matrix_a, 16, 16, 16, __half, wmma::row_major> af[4];
#pragma unroll
            for (int fm = 0; fm < 4; fm++)
                wmma::load_matrix_sync(af[fm], Ab + (wm * 64 + fm * 16) * G2A_LD + ks * 16, G2A_LD);
#pragma unroll
            for (int fn = 0; fn < 2; fn++) {
                wmma::fragment<wmma::matrix_b, 16, 16, 16, __half, wmma::row_major> bf;
                wmma::load_matrix_sync(bf, Bb + (ks * 16) * G2B_LD + wn * 32 + fn * 16, G2B_LD);
#pragma unroll
                for (int fm = 0; fm < 4; fm++)
                    wmma::mma_sync(acc[fm][fn], af[fm], bf, acc[fm][fn]);
            }
        }
    }
    CP_WAIT(0);
    __syncthreads();

    // epilogue via per-warp fp32 scratch (32 rows x 36 stride = 4608 B each)
    float* sw = (float*)dsmem + warp * (32 * 36);
#pragma unroll
    for (int hm = 0; hm < 2; hm++) {
#pragma unroll
        for (int fm2 = 0; fm2 < 2; fm2++)
#pragma unroll
            for (int fn = 0; fn < 2; fn++)
                wmma::store_matrix_sync(sw + fm2 * 16 * 36 + fn * 16,
                                        acc[hm * 2 + fm2][fn], 36, wmma::mem_row_major);
        __syncwarp();
        const int colbase = n0 + wn * 32;
#pragma unroll
        for (int it = 0; it < 8; it++) {
            int idx = lane + it * 32;
            int r  = idx >> 3;
            int c4 = (idx & 7) << 2;
            float4 v = *(float4*)(sw + r * 36 + c4);
            int row = m0 + wm * 64 + hm * 32 + r;
            int col = colbase + c4;
            float4 bv = *(const float4*)(bias + col);
            v.x += bv.x; v.y += bv.y; v.z += bv.z; v.w += bv.w;
            if (ACT == 1) {
                v.x = fmaxf(v.x, 0.f); v.y = fmaxf(v.y, 0.f);
                v.z = fmaxf(v.z, 0.f); v.w = fmaxf(v.w, 0.f);
            }
            if (ACT == 2) {
                const float* Rf = (const float*)Rv;
                float4 rv = *(const float4*)(Rf + (size_t)row * ldr + col);
                v.x += rv.x; v.y += rv.y; v.z += rv.z; v.w += rv.w;
            }
            if (ACT == 3) {
                const __half* Rh = (const __half*)Rv;
                float hs[4], ht[4];
                uint2 u1 = *(const uint2*)(Rh + (size_t)row * ldr + col);
                uint2 u2 = *(const uint2*)(Rh + (size_t)row * ldr + 512 + col);
                {
                    __half2* hh = (__half2*)&u1;
                    float2 t0 = __half22float2(hh[0]), t1 = __half22float2(hh[1]);
                    hs[0] = t0.x; hs[1] = t0.y; hs[2] = t1.x; hs[3] = t1.y;
                }
                {
                    __half2* hh = (__half2*)&u2;
                    float2 t0 = __half22float2(hh[0]), t1 = __half22float2(hh[1]);
                    ht[0] = t0.x; ht[1] = t0.y; ht[2] = t1.x; ht[3] = t1.y;
                }
                float zx = 1.f / (1.f + __expf(-v.x));
                float zy = 1.f / (1.f + __expf(-v.y));
                float zz = 1.f / (1.f + __expf(-v.z));
                float zw = 1.f / (1.f + __expf(-v.w));
                v.x = zx * hs[0] + (1.f - zx) * ht[0];
                v.y = zy * hs[1] + (1.f - zy) * ht[1];
                v.z = zz * hs[2] + (1.f - zz) * ht[2];
                v.w = zw * hs[3] + (1.f - zw) * ht[3];
            }
            if constexpr (sizeof(OutT) == 2) {
                *(uint2*)((__half*)C + (size_t)row * ldc + col) = f4_to_h4(v);
            } else {
                *(float4*)((float*)C + (size_t)row * ldc + col) = v;
            }
        }
        __syncwarp();
    }
}

// ---------------- spatial attention: wmma flash, O resident in fragments ----------------
#define SA_QS_OFF   0
#define SA_KS_OFF   18432
#define SA_VS_OFF   27648
#define SA_SC_OFF   36864
#define SA_PS_OFF   71680
#define SA_RS_OFF   90112
#define SA_SMEM     90624

__global__ void __launch_bounds__(256, 2) spatial_attn_wmma_k(const __half* __restrict__ P,
                                                              __half* __restrict__ HS)
{
    extern __shared__ __align__(16) char dsm[];
    __half* Qs = (__half*)(dsm + SA_QS_OFF);   // [128][72]
    __half* Ks = (__half*)(dsm + SA_KS_OFF);   // [64][72]
    __half* Vs = (__half*)(dsm + SA_VS_OFF);   // [64][72]
    float*  Sc = (float*)(dsm + SA_SC_OFF);    // 8 x [16][68]
    __half* Ps = (__half*)(dsm + SA_PS_OFF);   // 8 x [16][72]
    float*  Rs = (float*)(dsm + SA_RS_OFF);    // 8 x [16] rescale factors

    const int tid  = threadIdx.x;
    const int w    = tid >> 5;
    const int lane = tid & 31;
    const int q0   = blockIdx.x * 128;
    const int h    = blockIdx.y;
    const int bt   = blockIdx.z;

    const __half* base = P + (size_t)bt * NN * C3;

    for (int idx = tid; idx < 1024; idx += 256) {
        int row = idx >> 3, c8 = (idx & 7) << 3;
        *(uint4*)(Qs + row * 72 + c8) =
            *(const uint4*)(base + (size_t)(q0 + row) * C3 + h * HD + c8);
    }
    __syncthreads();

    wmma::fragment<wmma::matrix_a, 16, 16, 16, __half, wmma::row_major> qf[4];
#pragma unroll
    for (int i = 0; i < 4; i++)
        wmma::load_matrix_sync(qf[i], Qs + (w * 16) * 72 + i * 16, 72);

    float* Sw  = Sc + w * 1088;
    __half* Pw = Ps + w * 1152;
    float* Rw  = Rs + w * 16;
    const int r  = lane >> 1;
    const int hf = lane & 1;
    const int g  = lane >> 2;            // accumulator row group

    // O accumulators stay in fragments across all tiles
    wmma::fragment<wmma::accumulator, 16, 16, 16, float> of[4];
#pragma unroll
    for (int j = 0; j < 4; j++) wmma::fill_fragment(of[j], 0.f);

    float m = -1e30f, l = 0.f;

    for (int tile = 0; tile < 8; tile++) {
        __syncthreads();
        for (int idx = tid; idx < 512; idx += 256) {
            int row = idx >> 3, c8 = (idx & 7) << 3;
            const __half* rp = base + (size_t)(tile * 64 + row) * C3 + h * HD + c8;
            *(uint4*)(Ks + row * 72 + c8) = *(const uint4*)(rp + 512);
            *(uint4*)(Vs + row * 72 + c8) = *(const uint4*)(rp + 1024);
        }
        __syncthreads();

        // S = Q @ K^T
        wmma::fragment<wmma::accumulator, 16, 16, 16, float> sf[4];
#pragma unroll
        for (int j = 0; j < 4; j++) wmma::fill_fragment(sf[j], 0.f);
#pragma unroll
        for (int i = 0; i < 4; i++) {
#pragma unroll
            for (int j = 0; j < 4; j++) {
                wmma::fragment<wmma::matrix_b, 16, 16, 16, __half, wmma::col_major> bf;
                wmma::load_matrix_sync(bf, Ks + (j * 16) * 72 + i * 16, 72);
                wmma::mma_sync(sf[j], qf[i], bf, sf[j]);
            }
        }
#pragma unroll
        for (int j = 0; j < 4; j++)
            wmma::store_matrix_sync(Sw + j * 16, sf[j], 68, wmma::mem_row_major);
        __syncwarp();

        // online softmax on row r (two threads per row)
        const float* srow = Sw + r * 68 + hf * 32;
        float mx = -1e30f;
#pragma unroll
        for (int j = 0; j < 32; j++) mx = fmaxf(mx, srow[j]);
        mx = fmaxf(mx, __shfl_xor_sync(0xffffffffu, mx, 1));
        float tm = mx * 0.125f;
        float nm = fmaxf(m, tm);
        float rf = __expf(m - nm);
        float ps = 0.f;
        __half* prow = Pw + r * 72 + hf * 32;
#pragma unroll
        for (int j = 0; j < 32; j += 2) {
            float p0 = __expf(srow[j] * 0.125f - nm);
            float p1 = __expf(srow[j + 1] * 0.125f - nm);
            ps += p0 + p1;
            *(__half2*)(prow + j) = __floats2half2_rn(p0, p1);
        }
        ps += __shfl_xor_sync(0xffffffffu, ps, 1);
        l = l * rf + ps;
        m = nm;
        if (hf == 0) Rw[r] = rf;
        __syncwarp();

        // rescale O fragments in place (row = g for elems {0,1,4,5}, g+8 for {2,3,6,7})
        float r0 = Rw[g], r1 = Rw[g + 8];
#pragma unroll
        for (int j = 0; j < 4; j++)
#pragma unroll
            for (int e = 0; e < 8; e++)
                of[j].x[e] *= ((e >> 1) & 1) ? r1 : r0;

        // O += P @ V (accumulate directly into fragments)
#pragma unroll
        for (int i = 0; i < 4; i++) {
            wmma::fragment<wmma::matrix_a, 16, 16, 16, __half, wmma::row_major> af;
            wmma::load_matrix_sync(af, Pw + i * 16, 72);
#pragma unroll
            for (int j = 0; j < 4; j++) {
                wmma::fragment<wmma::matrix_b, 16, 16, 16, __half, wmma::row_major> bf;
                wmma::load_matrix_sync(bf, Vs + (i * 16) * 72 + j * 16, 72);
                wmma::mma_sync(of[j], af, bf, of[j]);
            }
        }
        __syncwarp();
    }

    // final: dump O fragments once, normalize by 1/l, write out
#pragma unroll
    for (int j = 0; j < 4; j++)
        wmma::store_matrix_sync(Sw + j * 16, of[j], 68, wmma::mem_row_major);
    __syncwarp();
    float inv = 1.f / l;
    const float* orow = Sw + r * 68 + hf * 32;
    __half* op = HS + (size_t)(bt * NN + q0 + w * 16 + r) * 512 + h * HD + hf * 32;
#pragma unroll
    for (int i = 0; i < 8; i++) {
        float4 v = make_float4(orow[4 * i] * inv, orow[4 * i + 1] * inv,
                               orow[4 * i + 2] * inv, orow[4 * i + 3] * inv);
        *(uint2*)(op + i * 4) = f4_to_h4(v);
    }
}

// ---------------- temporal attention (causal over T=24, fp16 P) ----------------
__global__ void __launch_bounds__(192) temporal_attn_k(const __half* __restrict__ P,
                                                       __half* __restrict__ HT)
{
    const int n = blockIdx.x;
    const int b = blockIdx.y;
    const int h = threadIdx.x & 7;
    const int t = threadIdx.x >> 3;

    float q[64];
    {
        const uint4* qp = (const uint4*)(P + ((size_t)(b * TT + t) * NN + n) * C3 + 1536 + h * HD);
#pragma unroll
        for (int i = 0; i < 8; i++) h8_to_f8(__ldg(qp + i), q + 8 * i);
    }
    float o[64];
#pragma unroll
    for (int i = 0; i < 64; i++) o[i] = 0.f;
    float mr = -1e30f, l = 0.f;

    for (int s = 0; s <= t; s++) {
        size_t rk = ((size_t)(b * TT + s) * NN + n) * C3;
        const uint4* kp = (const uint4*)(P + rk + 2048 + h * HD);
        const uint4* vp = (const uint4*)(P + rk + 2560 + h * HD);
        float kb[64];
#pragma unroll
        for (int i = 0; i < 8; i++) h8_to_f8(__ldg(kp + i), kb + 8 * i);
        float s0 = 0.f, s1 = 0.f, s2 = 0.f, s3 = 0.f;
#pragma unroll
        for (int c = 0; c < 16; c++) {
            s0 += q[4 * c]     * kb[4 * c];
            s1 += q[4 * c + 1] * kb[4 * c + 1];
            s2 += q[4 * c + 2] * kb[4 * c + 2];
            s3 += q[4 * c + 3] * kb[4 * c + 3];
        }
        float sc = ((s0 + s1) + (s2 + s3)) * 0.125f;
        float vb[64];
#pragma unroll
        for (int i = 0; i < 8; i++) h8_to_f8(__ldg(vp + i), vb + 8 * i);
        if (sc <= mr) {
            float p = __expf(sc - mr);
            l += p;
#pragma unroll
            for (int c = 0; c < 64; c++) o[c] += p * vb[c];
        } else {
            float r = __expf(mr - sc);
            mr = sc;
            l = l * r + 1.f;
#pragma unroll
            for (int c = 0; c < 64; c++) o[c] = o[c] * r + vb[c];
        }
    }
    float inv = 1.f / l;
    __half* op = HT + ((size_t)(b * TT + t) * NN + n) * 512 + h * HD;
#pragma unroll
    for (int i = 0; i < 16; i++) {
        float4 v = make_float4(o[4 * i] * inv, o[4 * i + 1] * inv,
                               o[4 * i + 2] * inv, o[4 * i + 3] * inv);
        *(uint2*)(op + 4 * i) = f4_to_h4(v);
    }
}

// ---------------- launch ----------------
extern "C" void kernel_launch(void* const* d_in, const int* in_sizes, int n_in,
                              void* d_out, int out_size)
{
    const float* X    = (const float*)d_in[0];
    const float* STE  = (const float*)d_in[1];
    const float* sWq  = (const float*)d_in[2];
    const float* sbq  = (const float*)d_in[3];
    const float* sWk  = (const float*)d_in[4];
    const float* sbk  = (const float*)d_in[5];
    const float* sWv  = (const float*)d_in[6];
    const float* sbv  = (const float*)d_in[7];
    const float* sWo  = (const float*)d_in[8];
    const float* sbo  = (const float*)d_in[9];
    const float* tWq  = (const float*)d_in[10];
    const float* tbq  = (const float*)d_in[11];
    const float* tWk  = (const float*)d_in[12];
    const float* tbk  = (const float*)d_in[13];
    const float* tWv  = (const float*)d_in[14];
    const float* tbv  = (const float*)d_in[15];
    const float* tWo  = (const float*)d_in[16];
    const float* tbo  = (const float*)d_in[17];
    const float* gWxs = (const float*)d_in[18];
    const float* gWxt = (const float*)d_in[19];
    const float* gbxt = (const float*)d_in[20];
    const float* gWh1 = (const float*)d_in[21];
    const float* gbh1 = (const float*)d_in[22];
    const float* gWh2 = (const float*)d_in[23];
    const float* gbh2 = (const float*)d_in[24];
    float* out = (float*)d_out;

    __half *Xh, *Ph, *Wch, *Wgh, *sWoh, *tWoh, *Wh1h, *Wh2h, *HSh, *HTh, *HSTh;
    float *bcat;
    cudaGetSymbolAddress((void**)&Xh,   g_Xh);
    cudaGetSymbolAddress((void**)&Ph,   g_Ph);
    cudaGetSymbolAddress((void**)&Wch,  g_Wch);
    cudaGetSymbolAddress((void**)&bcat, g_bcat);
    cudaGetSymbolAddress((void**)&Wgh,  g_Wgh);
    cudaGetSymbolAddress((void**)&sWoh, g_sWoh);
    cudaGetSymbolAddress((void**)&tWoh, g_tWoh);
    cudaGetSymbolAddress((void**)&Wh1h, g_Wh1h);
    cudaGetSymbolAddress((void**)&Wh2h, g_Wh2h);
    cudaGetSymbolAddress((void**)&HSh,  g_HSh);
    cudaGetSymbolAddress((void**)&HTh,  g_HTh);
    cudaGetSymbolAddress((void**)&HSTh, g_HSTh);

    static int attr_set = 0;
    if (!attr_set) {
        cudaFuncSetAttribute(spatial_attn_wmma_k,
                             cudaFuncAttributeMaxDynamicSharedMemorySize, SA_SMEM);
        cudaFuncSetAttribute(gemm2_k<1, __half>,
                             cudaFuncAttributeMaxDynamicSharedMemorySize, G2SMEM);
        cudaFuncSetAttribute(gemm2_k<3, __half>,
                             cudaFuncAttributeMaxDynamicSharedMemorySize, G2SMEM);
        cudaFuncSetAttribute(gemm2_k<2, float>,
                             cudaFuncAttributeMaxDynamicSharedMemorySize, G2SMEM);
        attr_set = 1;
    }

    // 1) fp16 conversions
    conv_xc_h<<<(MROWS * 384 + 255) / 256, 256>>>(X, STE, Xh);
    prep_weights_k<<<(PW_R4 + 255) / 256, 256>>>(
        sWq, sWk, sWv, tWq, tWk, tWv,
        sbq, sbk, sbv, tbq, tbk, tbv,
        gWxs, gWxt, sWo, tWo, gWh1, gWh2,
        Wch, Wgh, sWoh, tWoh, Wh1h, Wh2h, bcat);

    // 2) six projections in one GEMM: Ph = relu(Xh @ Wch + bcat)
    gemm2_k<1, __half><<<dim3(24, 96), 512, G2SMEM>>>(
        Xh, Wch, bcat, nullptr, Ph, 1536, 1536, 3072, 3072, 0);

    // 3) attention
    spatial_attn_wmma_k<<<dim3(4, NH, BB * TT), 256, SA_SMEM>>>(Ph, HSh);
    temporal_attn_k<<<dim3(NN, BB), 192>>>(Ph, HTh);

    // 4) output projections into HSTh = [relu(HS@sWo+b) | relu(HT@tWo+b)]
    gemm2_k<1, __half><<<dim3(4, 96), 512, G2SMEM>>>(
        HSh, sWoh, sbo, nullptr, HSTh, 512, 512, 512, 1024, 0);
    gemm2_k<1, __half><<<dim3(4, 96), 512, G2SMEM>>>(
        HTh, tWoh, tbo, nullptr, HSTh + 512, 512, 512, 512, 1024, 0);

    // 5) gated fusion fused in epilogue: H1 = sig(HST@Wg+b)*HSp + (1-sig)*HTp -> HSh
    gemm2_k<3, __half><<<dim3(4, 96), 512, G2SMEM>>>(
        HSTh, Wgh, gbxt, HSTh, HSh, 1024, 1024, 512, 512, 1024);

    // 6) MLP: H2 = relu(H1 @ gWh1 + gbh1) -> HTh
    gemm2_k<1, __half><<<dim3(4, 96), 512, G2SMEM>>>(
        HSh, Wh1h, gbh1, nullptr, HTh, 512, 512, 512, 512, 0);
    // out = X + H2 @ gWh2 + gbh2   (fp32 out)
    gemm2_k<2, float><<<dim3(4, 96), 512, G2SMEM>>>(
        HTh, Wh2h, gbh2, X, out, 512, 512, 512, 512, 512);
}

// round 11
// speedup vs baseline: 1.1326x; 1.1326x over previous
#include <cuda_runtime.h>
#include <cuda_fp16.h>
#include <cstdint>
#include <mma.h>
using namespace nvcuda;

// ---------------- problem constants ----------------
#define BB 2
#define TT 24
#define NN 512
#define DD 512
#define NH 8
#define HD 64
#define MROWS (BB*TT*NN)      // 24576
#define C3 3072               // P row stride: [sQ sK sV tQ tK tV]

// ---------------- scratch (static device globals; no allocation) ----------------
__device__ __half g_Xh [(size_t)MROWS * 1536];
__device__ __half g_Ph [(size_t)MROWS * 3072];
__device__ __half g_Wch[1536 * 3072];
__device__ float  g_bcat[3072];
__device__ __half g_Wgh[1024 * 512];
__device__ __half g_sWoh[512 * 512];
__device__ __half g_tWoh[512 * 512];
__device__ __half g_Wh1h[512 * 512];
__device__ __half g_Wh2h[512 * 512];
__device__ __half g_HSh [(size_t)MROWS * 512];
__device__ __half g_HTh [(size_t)MROWS * 512];
__device__ __half g_HSTh[(size_t)MROWS * 1024];

__device__ __forceinline__ uint2 f4_to_h4(float4 v) {
    __half2 a = __floats2half2_rn(v.x, v.y);
    __half2 b = __floats2half2_rn(v.z, v.w);
    uint2 r;
    r.x = *(unsigned*)&a;
    r.y = *(unsigned*)&b;
    return r;
}

__device__ __forceinline__ void h8_to_f8(uint4 u, float* f) {
    __half2* h = (__half2*)&u;
#pragma unroll
    for (int i = 0; i < 4; i++) {
        float2 t = __half22float2(h[i]);
        f[2 * i] = t.x; f[2 * i + 1] = t.y;
    }
}

#define CP_ASYNC16(dst, src) \
    asm volatile("cp.async.cg.shared.global [%0], [%1], 16;\n" :: "r"(dst), "l"(src))
#define CP_COMMIT() asm volatile("cp.async.commit_group;\n")
#define CP_WAIT(n)  asm volatile("cp.async.wait_group %0;\n" :: "n"(n))

// ---------------- conversion kernels ----------------
__global__ void conv_xc_h(const float* __restrict__ X, const float* __restrict__ STE,
                          __half* __restrict__ Xh)
{
    int idx = blockIdx.x * blockDim.x + threadIdx.x;
    if (idx >= MROWS * 384) return;
    int m = idx / 384, c4 = idx % 384;
    float4 v;
    if (c4 < 128) v = ((const float4*)X)[(size_t)m * 128 + c4];
    else          v = ((const float4*)STE)[(size_t)m * 256 + (c4 - 128)];
    *(uint2*)(Xh + (size_t)idx * 4) = f4_to_h4(v);
}

#define PW_R1 1179648
#define PW_R2 (PW_R1 + 131072)
#define PW_R3 (PW_R2 + 262144)
#define PW_R4 (PW_R3 + 768)
__global__ void prep_weights_k(
    const float* __restrict__ w0, const float* __restrict__ w1,
    const float* __restrict__ w2, const float* __restrict__ w3,
    const float* __restrict__ w4, const float* __restrict__ w5,
    const float* __restrict__ b0, const float* __restrict__ b1,
    const float* __restrict__ b2, const float* __restrict__ b3,
    const float* __restrict__ b4, const float* __restrict__ b5,
    const float* __restrict__ wxs, const float* __restrict__ wxt,
    const float* __restrict__ sWo, const float* __restrict__ tWo,
    const float* __restrict__ wh1, const float* __restrict__ wh2,
    __half* __restrict__ Wch, __half* __restrict__ Wgh,
    __half* __restrict__ sWoh, __half* __restrict__ tWoh,
    __half* __restrict__ Wh1h, __half* __restrict__ Wh2h,
    float* __restrict__ bcat)
{
    int idx = blockIdx.x * blockDim.x + threadIdx.x;
    if (idx < PW_R1) {
        int k = idx / 768, q = idx % 768;
        int j = q >> 7, cq = q & 127;
        const float* ws[6] = {w0, w1, w2, w3, w4, w5};
        float4 v = *(const float4*)(ws[j] + k * 512 + cq * 4);
        *(uint2*)(Wch + (size_t)k * 3072 + j * 512 + cq * 4) = f4_to_h4(v);
    } else if (idx < PW_R2) {
        int e = idx - PW_R1;
        int k = e >> 7, cq = e & 127;
        const float* src = (k < 512) ? (wxs + k * 512) : (wxt + (k - 512) * 512);
        float4 v = *(const float4*)(src + cq * 4);
        *(uint2*)(Wgh + (size_t)k * 512 + cq * 4) = f4_to_h4(v);
    } else if (idx < PW_R3) {
        int e = idx - PW_R2;
        int which = e >> 16, q = e & 65535;
        const float* w = (which == 0) ? sWo : (which == 1) ? tWo : (which == 2) ? wh1 : wh2;
        __half* o = (which == 0) ? sWoh : (which == 1) ? tWoh : (which == 2) ? Wh1h : Wh2h;
        float4 v = *(const float4*)(w + q * 4);
        *(uint2*)(o + (size_t)q * 4) = f4_to_h4(v);
    } else if (idx < PW_R4) {
        int e = idx - PW_R3;
        int j = e >> 7, c = e & 127;
        const float* bs[6] = {b0, b1, b2, b3, b4, b5};
        *(float4*)(bcat + j * 512 + c * 4) = *(const float4*)(bs[j] + c * 4);
    }
}

// ---------------- fp16 tensor GEMM 128x128, BK=32, 4-stage cp.async ----------------
// ACT: 0 bias, 1 bias+relu, 2 bias+residual(float R), 3 gated fusion(half R)
#define GA_LDH 40
#define GB_LDH 136
#define GAS (128 * GA_LDH)
#define GBS (32 * GB_LDH)
#define NSTAGE 4
#define GSMEM_DYN (NSTAGE * (GAS + GBS) * 2)   // 75776 B

template<int ACT, typename OutT>
__global__ void __launch_bounds__(256, 2) gemm_cp_k(
    const __half* __restrict__ A, const __half* __restrict__ B,
    const float* __restrict__ bias, const void* __restrict__ Rv,
    OutT* __restrict__ C, int M, int N, int K, int lda, int ldb, int ldc, int ldr)
{
    extern __shared__ __align__(16) char dsmem[];
    __half* As = (__half*)dsmem;
    __half* Bs = (__half*)dsmem + NSTAGE * GAS;

    const int tid  = threadIdx.x;
    const int warp = tid >> 5;
    const int lane = tid & 31;
    const int wm   = warp & 3;
    const int wn   = warp >> 2;
    const int m0 = blockIdx.y * 128;
    const int n0 = blockIdx.x * 128;

    const int a_row = tid >> 2;
    const int a_c8  = (tid & 3) << 3;
    const int b_row = tid >> 4;
    const int b_c8  = (tid & 15) << 3;

    const unsigned int sA = (unsigned int)__cvta_generic_to_shared(As);
    const unsigned int sB = (unsigned int)__cvta_generic_to_shared(Bs);

    const int nk = K >> 5;

    auto issue = [&](int kt, int stage) {
        int k0 = kt << 5;
        CP_ASYNC16(sA + (stage * GAS + a_row * GA_LDH + a_c8) * 2,
                   A + (size_t)(m0 + a_row) * lda + k0 + a_c8);
        CP_ASYNC16(sA + (stage * GAS + (64 + a_row) * GA_LDH + a_c8) * 2,
                   A + (size_t)(m0 + 64 + a_row) * lda + k0 + a_c8);
        CP_ASYNC16(sB + (stage * GBS + b_row * GB_LDH + b_c8) * 2,
                   B + (size_t)(k0 + b_row) * ldb + n0 + b_c8);
        CP_ASYNC16(sB + (stage * GBS + (16 + b_row) * GB_LDH + b_c8) * 2,
                   B + (size_t)(k0 + 16 + b_row) * ldb + n0 + b_c8);
    };

    wmma::fragment<wmma::accumulator, 16, 16, 16, float> acc[2][4];
#pragma unroll
    for (int i = 0; i < 2; i++)
#pragma unroll
        for (int j = 0; j < 4; j++) wmma::fill_fragment(acc[i][j], 0.f);

#pragma unroll
    for (int s = 0; s < NSTAGE - 1; s++) {
        if (s < nk) issue(s, s);
        CP_COMMIT();
    }

    for (int kt = 0; kt < nk; kt++) {
        CP_WAIT(NSTAGE - 2);
        __syncthreads();

        int nx = kt + NSTAGE - 1;
        if (nx < nk) issue(nx, nx & (NSTAGE - 1));
        CP_COMMIT();

        const int buf = kt & (NSTAGE - 1);
        const __half* Ab = As + buf * GAS;
        const __half* Bb = Bs + buf * GBS;
#pragma unroll
        for (int ks = 0; ks < 2; ks++) {
            wmma::fragment<wmma::matrix_a, 16, 16, 16, __half, wmma::row_major> af[2];
#pragma unroll
            for (int fm = 0; fm < 2; fm++)
                wmma::load_matrix_sync(af[fm], Ab + (wm * 32 + fm * 16) * GA_LDH + ks * 16, GA_LDH);
#pragma unroll
            for (int fn = 0; fn < 4; fn++) {
                wmma::fragment<wmma::matrix_b, 16, 16, 16, __half, wmma::row_major> bf;
                wmma::load_matrix_sync(bf, Bb + (ks * 16) * GB_LDH + wn * 64 + fn * 16, GB_LDH);
#pragma unroll
                for (int fm = 0; fm < 2; fm++)
                    wmma::mma_sync(acc[fm][fn], af[fm], bf, acc[fm][fn]);
            }
        }
    }
    CP_WAIT(0);
    __syncthreads();

    float* sw = (float*)dsmem + warp * (32 * 40);
#pragma unroll
    for (int h = 0; h < 2; h++) {
#pragma unroll
        for (int fm = 0; fm < 2; fm++)
#pragma unroll
            for (int fnl = 0; fnl < 2; fnl++)
                wmma::store_matrix_sync(sw + fm * 16 * 40 + fnl * 16,
                                        acc[fm][h * 2 + fnl], 40, wmma::mem_row_major);
        __syncwarp();
        const int colbase = n0 + wn * 64 + h * 32;
#pragma unroll
        for (int i = 0; i < 8; i++) {
            int idx = lane + i * 32;
            int r  = idx >> 3;
            int c4 = (idx & 7) << 2;
            float4 v = *(float4*)(sw + r * 40 + c4);
            int row = m0 + wm * 32 + r;
            int col = colbase + c4;
            float4 bv = *(const float4*)(bias + col);
            v.x += bv.x; v.y += bv.y; v.z += bv.z; v.w += bv.w;
            if (ACT == 1) {
                v.x = fmaxf(v.x, 0.f); v.y = fmaxf(v.y, 0.f);
                v.z = fmaxf(v.z, 0.f); v.w = fmaxf(v.w, 0.f);
            }
            if (ACT == 2) {
                const float* Rf = (const float*)Rv;
                float4 rv = *(const float4*)(Rf + (size_t)row * ldr + col);
                v.x += rv.x; v.y += rv.y; v.z += rv.z; v.w += rv.w;
            }
            if (ACT == 3) {
                const __half* Rh = (const __half*)Rv;
                float hs[4], ht[4];
                uint2 u1 = *(const uint2*)(Rh + (size_t)row * ldr + col);
                uint2 u2 = *(const uint2*)(Rh + (size_t)row * ldr + 512 + col);
                {
                    __half2* hh = (__half2*)&u1;
                    float2 t0 = __half22float2(hh[0]), t1 = __half22float2(hh[1]);
                    hs[0] = t0.x; hs[1] = t0.y; hs[2] = t1.x; hs[3] = t1.y;
                }
                {
                    __half2* hh = (__half2*)&u2;
                    float2 t0 = __half22float2(hh[0]), t1 = __half22float2(hh[1]);
                    ht[0] = t0.x; ht[1] = t0.y; ht[2] = t1.x; ht[3] = t1.y;
                }
                float zx = 1.f / (1.f + __expf(-v.x));
                float zy = 1.f / (1.f + __expf(-v.y));
                float zz = 1.f / (1.f + __expf(-v.z));
                float zw = 1.f / (1.f + __expf(-v.w));
                v.x = zx * hs[0] + (1.f - zx) * ht[0];
                v.y = zy * hs[1] + (1.f - zy) * ht[1];
                v.z = zz * hs[2] + (1.f - zz) * ht[2];
                v.w = zw * hs[3] + (1.f - zw) * ht[3];
            }
            if constexpr (sizeof(OutT) == 2) {
                *(uint2*)((__half*)C + (size_t)row * ldc + col) = f4_to_h4(v);
            } else {
                *(float4*)((float*)C + (size_t)row * ldc + col) = v;
            }
        }
        __syncwarp();
    }
}

// ---------------- spatial attention: wmma flash, O resident in fragments ----------------
#define SA_QS_OFF   0
#define SA_KS_OFF   18432
#define SA_VS_OFF   27648
#define SA_SC_OFF   36864
#define SA_PS_OFF   71680
#define SA_RS_OFF   90112
#define SA_SMEM     90624

__global__ void __launch_bounds__(256, 2) spatial_attn_wmma_k(const __half* __restrict__ P,
                                                              __half* __restrict__ HS)
{
    extern __shared__ __align__(16) char dsm[];
    __half* Qs = (__half*)(dsm + SA_QS_OFF);   // [128][72]
    __half* Ks = (__half*)(dsm + SA_KS_OFF);   // [64][72]
    __half* Vs = (__half*)(dsm + SA_VS_OFF);   // [64][72]
    float*  Sc = (float*)(dsm + SA_SC_OFF);    // 8 x [16][68]
    __half* Ps = (__half*)(dsm + SA_PS_OFF);   // 8 x [16][72]
    float*  Rs = (float*)(dsm + SA_RS_OFF);    // 8 x [16]

    const int tid  = threadIdx.x;
    const int w    = tid >> 5;
    const int lane = tid & 31;
    const int q0   = blockIdx.x * 128;
    const int h    = blockIdx.y;
    const int bt   = blockIdx.z;

    const __half* base = P + (size_t)bt * NN * C3;

    for (int idx = tid; idx < 1024; idx += 256) {
        int row = idx >> 3, c8 = (idx & 7) << 3;
        *(uint4*)(Qs + row * 72 + c8) =
            *(const uint4*)(base + (size_t)(q0 + row) * C3 + h * HD + c8);
    }
    __syncthreads();

    wmma::fragment<wmma::matrix_a, 16, 16, 16, __half, wmma::row_major> qf[4];
#pragma unroll
    for (int i = 0; i < 4; i++)
        wmma::load_matrix_sync(qf[i], Qs + (w * 16) * 72 + i * 16, 72);

    float* Sw  = Sc + w * 1088;
    __half* Pw = Ps + w * 1152;
    float* Rw  = Rs + w * 16;
    const int r  = lane >> 1;
    const int hf = lane & 1;
    const int g  = lane >> 2;

    wmma::fragment<wmma::accumulator, 16, 16, 16, float> of[4];
#pragma unroll
    for (int j = 0; j < 4; j++) wmma::fill_fragment(of[j], 0.f);

    float m = -1e30f, l = 0.f;

    for (int tile = 0; tile < 8; tile++) {
        __syncthreads();
        for (int idx = tid; idx < 512; idx += 256) {
            int row = idx >> 3, c8 = (idx & 7) << 3;
            const __half* rp = base + (size_t)(tile * 64 + row) * C3 + h * HD + c8;
            *(uint4*)(Ks + row * 72 + c8) = *(const uint4*)(rp + 512);
            *(uint4*)(Vs + row * 72 + c8) = *(const uint4*)(rp + 1024);
        }
        __syncthreads();

        wmma::fragment<wmma::accumulator, 16, 16, 16, float> sf[4];
#pragma unroll
        for (int j = 0; j < 4; j++) wmma::fill_fragment(sf[j], 0.f);
#pragma unroll
        for (int i = 0; i < 4; i++) {
#pragma unroll
            for (int j = 0; j < 4; j++) {
                wmma::fragment<wmma::matrix_b, 16, 16, 16, __half, wmma::col_major> bf;
                wmma::load_matrix_sync(bf, Ks + (j * 16) * 72 + i * 16, 72);
                wmma::mma_sync(sf[j], qf[i], bf, sf[j]);
            }
        }
#pragma unroll
        for (int j = 0; j < 4; j++)
            wmma::store_matrix_sync(Sw + j * 16, sf[j], 68, wmma::mem_row_major);
        __syncwarp();

        const float* srow = Sw + r * 68 + hf * 32;
        float mx = -1e30f;
#pragma unroll
        for (int j = 0; j < 32; j++) mx = fmaxf(mx, srow[j]);
        mx = fmaxf(mx, __shfl_xor_sync(0xffffffffu, mx, 1));
        float tm = mx * 0.125f;
        float nm = fmaxf(m, tm);
        float rf = __expf(m - nm);
        float ps = 0.f;
        __half* prow = Pw + r * 72 + hf * 32;
#pragma unroll
        for (int j = 0; j < 32; j += 2) {
            float p0 = __expf(srow[j] * 0.125f - nm);
            float p1 = __expf(srow[j + 1] * 0.125f - nm);
            ps += p0 + p1;
            *(__half2*)(prow + j) = __floats2half2_rn(p0, p1);
        }
        ps += __shfl_xor_sync(0xffffffffu, ps, 1);
        l = l * rf + ps;
        m = nm;
        if (hf == 0) Rw[r] = rf;
        __syncwarp();

        float r0 = Rw[g], r1 = Rw[g + 8];
#pragma unroll
        for (int j = 0; j < 4; j++)
#pragma unroll
            for (int e = 0; e < 8; e++)
                of[j].x[e] *= ((e >> 1) & 1) ? r1 : r0;

#pragma unroll
        for (int i = 0; i < 4; i++) {
            wmma::fragment<wmma::matrix_a, 16, 16, 16, __half, wmma::row_major> af;
            wmma::load_matrix_sync(af, Pw + i * 16, 72);
#pragma unroll
            for (int j = 0; j < 4; j++) {
                wmma::fragment<wmma::matrix_b, 16, 16, 16, __half, wmma::row_major> bf;
                wmma::load_matrix_sync(bf, Vs + (i * 16) * 72 + j * 16, 72);
                wmma::mma_sync(of[j], af, bf, of[j]);
            }
        }
        __syncwarp();
    }

#pragma unroll
    for (int j = 0; j < 4; j++)
        wmma::store_matrix_sync(Sw + j * 16, of[j], 68, wmma::mem_row_major);
    __syncwarp();
    float inv = 1.f / l;
    const float* orow = Sw + r * 68 + hf * 32;
    __half* op = HS + (size_t)(bt * NN + q0 + w * 16 + r) * 512 + h * HD + hf * 32;
#pragma unroll
    for (int i = 0; i < 8; i++) {
        float4 v = make_float4(orow[4 * i] * inv, orow[4 * i + 1] * inv,
                               orow[4 * i + 2] * inv, orow[4 * i + 3] * inv);
        *(uint2*)(op + i * 4) = f4_to_h4(v);
    }
}

// ---------------- temporal attention (causal over T=24, fp16 P) ----------------
__global__ void __launch_bounds__(192) temporal_attn_k(const __half* __restrict__ P,
                                                       __half* __restrict__ HT)
{
    const int n = blockIdx.x;
    const int b = blockIdx.y;
    const int h = threadIdx.x & 7;
    const int t = threadIdx.x >> 3;

    float q[64];
    {
        const uint4* qp = (const uint4*)(P + ((size_t)(b * TT + t) * NN + n) * C3 + 1536 + h * HD);
#pragma unroll
        for (int i = 0; i < 8; i++) h8_to_f8(__ldg(qp + i), q + 8 * i);
    }
    float o[64];
#pragma unroll
    for (int i = 0; i < 64; i++) o[i] = 0.f;
    float mr = -1e30f, l = 0.f;

    for (int s = 0; s <= t; s++) {
        size_t rk = ((size_t)(b * TT + s) * NN + n) * C3;
        const uint4* kp = (const uint4*)(P + rk + 2048 + h * HD);
        const uint4* vp = (const uint4*)(P + rk + 2560 + h * HD);
        float kb[64];
#pragma unroll
        for (int i = 0; i < 8; i++) h8_to_f8(__ldg(kp + i), kb + 8 * i);
        float s0 = 0.f, s1 = 0.f, s2 = 0.f, s3 = 0.f;
#pragma unroll
        for (int c = 0; c < 16; c++) {
            s0 += q[4 * c]     * kb[4 * c];
            s1 += q[4 * c + 1] * kb[4 * c + 1];
            s2 += q[4 * c + 2] * kb[4 * c + 2];
            s3 += q[4 * c + 3] * kb[4 * c + 3];
        }
        float sc = ((s0 + s1) + (s2 + s3)) * 0.125f;
        float vb[64];
#pragma unroll
        for (int i = 0; i < 8; i++) h8_to_f8(__ldg(vp + i), vb + 8 * i);
        if (sc <= mr) {
            float p = __expf(sc - mr);
            l += p;
#pragma unroll
            for (int c = 0; c < 64; c++) o[c] += p * vb[c];
        } else {
            float r = __expf(mr - sc);
            mr = sc;
            l = l * r + 1.f;
#pragma unroll
            for (int c = 0; c < 64; c++) o[c] = o[c] * r + vb[c];
        }
    }
    float inv = 1.f / l;
    __half* op = HT + ((size_t)(b * TT + t) * NN + n) * 512 + h * HD;
#pragma unroll
    for (int i = 0; i < 16; i++) {
        float4 v = make_float4(o[4 * i] * inv, o[4 * i + 1] * inv,
                               o[4 * i + 2] * inv, o[4 * i + 3] * inv);
        *(uint2*)(op + 4 * i) = f4_to_h4(v);
    }
}

// ---------------- launch ----------------
extern "C" void kernel_launch(void* const* d_in, const int* in_sizes, int n_in,
                              void* d_out, int out_size)
{
    const float* X    = (const float*)d_in[0];
    const float* STE  = (const float*)d_in[1];
    const float* sWq  = (const float*)d_in[2];
    const float* sbq  = (const float*)d_in[3];
    const float* sWk  = (const float*)d_in[4];
    const float* sbk  = (const float*)d_in[5];
    const float* sWv  = (const float*)d_in[6];
    const float* sbv  = (const float*)d_in[7];
    const float* sWo  = (const float*)d_in[8];
    const float* sbo  = (const float*)d_in[9];
    const float* tWq  = (const float*)d_in[10];
    const float* tbq  = (const float*)d_in[11];
    const float* tWk  = (const float*)d_in[12];
    const float* tbk  = (const float*)d_in[13];
    const float* tWv  = (const float*)d_in[14];
    const float* tbv  = (const float*)d_in[15];
    const float* tWo  = (const float*)d_in[16];
    const float* tbo  = (const float*)d_in[17];
    const float* gWxs = (const float*)d_in[18];
    const float* gWxt = (const float*)d_in[19];
    const float* gbxt = (const float*)d_in[20];
    const float* gWh1 = (const float*)d_in[21];
    const float* gbh1 = (const float*)d_in[22];
    const float* gWh2 = (const float*)d_in[23];
    const float* gbh2 = (const float*)d_in[24];
    float* out = (float*)d_out;

    __half *Xh, *Ph, *Wch, *Wgh, *sWoh, *tWoh, *Wh1h, *Wh2h, *HSh, *HTh, *HSTh;
    float *bcat;
    cudaGetSymbolAddress((void**)&Xh,   g_Xh);
    cudaGetSymbolAddress((void**)&Ph,   g_Ph);
    cudaGetSymbolAddress((void**)&Wch,  g_Wch);
    cudaGetSymbolAddress((void**)&bcat, g_bcat);
    cudaGetSymbolAddress((void**)&Wgh,  g_Wgh);
    cudaGetSymbolAddress((void**)&sWoh, g_sWoh);
    cudaGetSymbolAddress((void**)&tWoh, g_tWoh);
    cudaGetSymbolAddress((void**)&Wh1h, g_Wh1h);
    cudaGetSymbolAddress((void**)&Wh2h, g_Wh2h);
    cudaGetSymbolAddress((void**)&HSh,  g_HSh);
    cudaGetSymbolAddress((void**)&HTh,  g_HTh);
    cudaGetSymbolAddress((void**)&HSTh, g_HSTh);

    static int attr_set = 0;
    if (!attr_set) {
        cudaFuncSetAttribute(spatial_attn_wmma_k,
                             cudaFuncAttributeMaxDynamicSharedMemorySize, SA_SMEM);
        cudaFuncSetAttribute(gemm_cp_k<1, __half>,
                             cudaFuncAttributeMaxDynamicSharedMemorySize, GSMEM_DYN);
        cudaFuncSetAttribute(gemm_cp_k<3, __half>,
                             cudaFuncAttributeMaxDynamicSharedMemorySize, GSMEM_DYN);
        cudaFuncSetAttribute(gemm_cp_k<2, float>,
                             cudaFuncAttributeMaxDynamicSharedMemorySize, GSMEM_DYN);
        attr_set = 1;
    }

    // 1) fp16 conversions
    conv_xc_h<<<(MROWS * 384 + 255) / 256, 256>>>(X, STE, Xh);
    prep_weights_k<<<(PW_R4 + 255) / 256, 256>>>(
        sWq, sWk, sWv, tWq, tWk, tWv,
        sbq, sbk, sbv, tbq, tbk, tbv,
        gWxs, gWxt, sWo, tWo, gWh1, gWh2,
        Wch, Wgh, sWoh, tWoh, Wh1h, Wh2h, bcat);

    // 2) six projections in one GEMM: Ph = relu(Xh @ Wch + bcat)
    gemm_cp_k<1, __half><<<dim3(24, 192), 256, GSMEM_DYN>>>(
        Xh, Wch, bcat, nullptr, Ph, MROWS, 3072, 1536, 1536, 3072, 3072, 0);

    // 3) attention
    spatial_attn_wmma_k<<<dim3(4, NH, BB * TT), 256, SA_SMEM>>>(Ph, HSh);
    temporal_attn_k<<<dim3(NN, BB), 192>>>(Ph, HTh);

    // 4) output projections into HSTh = [relu(HS@sWo+b) | relu(HT@tWo+b)]
    gemm_cp_k<1, __half><<<dim3(4, 192), 256, GSMEM_DYN>>>(
        HSh, sWoh, sbo, nullptr, HSTh, MROWS, 512, 512, 512, 512, 1024, 0);
    gemm_cp_k<1, __half><<<dim3(4, 192), 256, GSMEM_DYN>>>(
        HTh, tWoh, tbo, nullptr, HSTh + 512, MROWS, 512, 512, 512, 512, 1024, 0);

    // 5) gated fusion fused in epilogue: H1 = sig(HST@Wg+b)*HSp + (1-sig)*HTp -> HSh
    gemm_cp_k<3, __half><<<dim3(4, 192), 256, GSMEM_DYN>>>(
        HSTh, Wgh, gbxt, HSTh, HSh, MROWS, 512, 1024, 1024, 512, 512, 1024);

    // 6) MLP: H2 = relu(H1 @ gWh1 + gbh1) -> HTh
    gemm_cp_k<1, __half><<<dim3(4, 192), 256, GSMEM_DYN>>>(
        HSh, Wh1h, gbh1, nullptr, HTh, MROWS, 512, 512, 512, 512, 512, 0);
    // out = X + H2 @ gWh2 + gbh2   (fp32 out)
    gemm_cp_k<2, float><<<dim3(4, 192), 256, GSMEM_DYN>>>(
        HTh, Wh2h, gbh2, X, out, MROWS, 512, 512, 512, 512, 512, 512);
}

// round 13
// speedup vs baseline: 1.2828x; 1.1326x over previous
#include <cuda_runtime.h>
#include <cuda_fp16.h>
#include <cstdint>
#include <mma.h>
using namespace nvcuda;

// ---------------- problem constants ----------------
#define BB 2
#define TT 24
#define NN 512
#define DD 512
#define NH 8
#define HD 64
#define MROWS (BB*TT*NN)      // 24576
#define C3 3072               // P row stride: [sQ sK sV tQ tK tV]

// ---------------- scratch (static device globals; no allocation) ----------------
__device__ __half g_Xh [(size_t)MROWS * 1536];
__device__ __half g_Ph [(size_t)MROWS * 3072];
__device__ __half g_Wch[1536 * 3072];
__device__ float  g_bcat[3072];
__device__ __half g_Wgh[1024 * 512];
__device__ __half g_sWoh[512 * 512];
__device__ __half g_tWoh[512 * 512];
__device__ __half g_Wh1h[512 * 512];
__device__ __half g_Wh2h[512 * 512];
__device__ __half g_HSh [(size_t)MROWS * 512];
__device__ __half g_HTh [(size_t)MROWS * 512];
__device__ __half g_HSTh[(size_t)MROWS * 1024];

__device__ __forceinline__ uint2 f4_to_h4(float4 v) {
    __half2 a = __floats2half2_rn(v.x, v.y);
    __half2 b = __floats2half2_rn(v.z, v.w);
    uint2 r;
    r.x = *(unsigned*)&a;
    r.y = *(unsigned*)&b;
    return r;
}

__device__ __forceinline__ void h8_to_f8(uint4 u, float* f) {
    __half2* h = (__half2*)&u;
#pragma unroll
    for (int i = 0; i < 4; i++) {
        float2 t = __half22float2(h[i]);
        f[2 * i] = t.x; f[2 * i + 1] = t.y;
    }
}

#define CP_ASYNC16(dst, src) \
    asm volatile("cp.async.cg.shared.global [%0], [%1], 16;\n" :: "r"(dst), "l"(src))
#define CP_COMMIT() asm volatile("cp.async.commit_group;\n")
#define CP_WAIT(n)  asm volatile("cp.async.wait_group %0;\n" :: "n"(n))

// ---------------- conversion kernels ----------------
__global__ void conv_xc_h(const float* __restrict__ X, const float* __restrict__ STE,
                          __half* __restrict__ Xh)
{
    int idx = blockIdx.x * blockDim.x + threadIdx.x;
    if (idx >= MROWS * 384) return;
    int m = idx / 384, c4 = idx % 384;
    float4 v;
    if (c4 < 128) v = ((const float4*)X)[(size_t)m * 128 + c4];
    else          v = ((const float4*)STE)[(size_t)m * 256 + (c4 - 128)];
    *(uint2*)(Xh + (size_t)idx * 4) = f4_to_h4(v);
}

#define PW_R1 1179648
#define PW_R2 (PW_R1 + 131072)
#define PW_R3 (PW_R2 + 262144)
#define PW_R4 (PW_R3 + 768)
__global__ void prep_weights_k(
    const float* __restrict__ w0, const float* __restrict__ w1,
    const float* __restrict__ w2, const float* __restrict__ w3,
    const float* __restrict__ w4, const float* __restrict__ w5,
    const float* __restrict__ b0, const float* __restrict__ b1,
    const float* __restrict__ b2, const float* __restrict__ b3,
    const float* __restrict__ b4, const float* __restrict__ b5,
    const float* __restrict__ wxs, const float* __restrict__ wxt,
    const float* __restrict__ sWo, const float* __restrict__ tWo,
    const float* __restrict__ wh1, const float* __restrict__ wh2,
    __half* __restrict__ Wch, __half* __restrict__ Wgh,
    __half* __restrict__ sWoh, __half* __restrict__ tWoh,
    __half* __restrict__ Wh1h, __half* __restrict__ Wh2h,
    float* __restrict__ bcat)
{
    int idx = blockIdx.x * blockDim.x + threadIdx.x;
    if (idx < PW_R1) {
        int k = idx / 768, q = idx % 768;
        int j = q >> 7, cq = q & 127;
        const float* ws[6] = {w0, w1, w2, w3, w4, w5};
        float4 v = *(const float4*)(ws[j] + k * 512 + cq * 4);
        *(uint2*)(Wch + (size_t)k * 3072 + j * 512 + cq * 4) = f4_to_h4(v);
    } else if (idx < PW_R2) {
        int e = idx - PW_R1;
        int k = e >> 7, cq = e & 127;
        const float* src = (k < 512) ? (wxs + k * 512) : (wxt + (k - 512) * 512);
        float4 v = *(const float4*)(src + cq * 4);
        *(uint2*)(Wgh + (size_t)k * 512 + cq * 4) = f4_to_h4(v);
    } else if (idx < PW_R3) {
        int e = idx - PW_R2;
        int which = e >> 16, q = e & 65535;
        const float* w = (which == 0) ? sWo : (which == 1) ? tWo : (which == 2) ? wh1 : wh2;
        __half* o = (which == 0) ? sWoh : (which == 1) ? tWoh : (which == 2) ? Wh1h : Wh2h;
        float4 v = *(const float4*)(w + q * 4);
        *(uint2*)(o + (size_t)q * 4) = f4_to_h4(v);
    } else if (idx < PW_R4) {
        int e = idx - PW_R3;
        int j = e >> 7, c = e & 127;
        const float* bs[6] = {b0, b1, b2, b3, b4, b5};
        *(float4*)(bcat + j * 512 + c * 4) = *(const float4*)(bs[j] + c * 4);
    }
}

// ---------------- fp16 tensor GEMM 128x128 CTA, 64x64 warp tile, BK=32, 4-stage ----------------
// 128 threads (4 warps, 2x2 warp grid).
// ACT: 0 bias, 1 bias+relu, 2 bias+residual(float R), 3 gated fusion(half R)
#define GA_LDH 40
#define GB_LDH 136
#define GAS (128 * GA_LDH)
#define GBS (32 * GB_LDH)
#define NSTAGE 4
#define GSMEM_DYN (NSTAGE * (GAS + GBS) * 2)   // 75776 B

template<int ACT, typename OutT>
__global__ void __launch_bounds__(128, 2) gemm_cp_k(
    const __half* __restrict__ A, const __half* __restrict__ B,
    const float* __restrict__ bias, const void* __restrict__ Rv,
    OutT* __restrict__ C, int M, int N, int K, int lda, int ldb, int ldc, int ldr)
{
    extern __shared__ __align__(16) char dsmem[];
    __half* As = (__half*)dsmem;
    __half* Bs = (__half*)dsmem + NSTAGE * GAS;

    const int tid  = threadIdx.x;
    const int warp = tid >> 5;
    const int lane = tid & 31;
    const int wm   = warp >> 1;   // 0..1 : 64-row subtile
    const int wn   = warp & 1;    // 0..1 : 64-col subtile
    const int m0 = blockIdx.y * 128;
    const int n0 = blockIdx.x * 128;

    const unsigned int sA = (unsigned int)__cvta_generic_to_shared(As);
    const unsigned int sB = (unsigned int)__cvta_generic_to_shared(Bs);

    const int nk = K >> 5;

    // each thread copies 4 A-chunks + 4 B-chunks (16B each) per stage
    auto issue = [&](int kt, int stage) {
        int k0 = kt << 5;
#pragma unroll
        for (int i = 0; i < 4; i++) {
            int ch = tid + i * 128;                 // 0..511
            int ar = ch >> 2, ac8 = (ch & 3) << 3;  // A: 128 rows x 32 cols
            CP_ASYNC16(sA + (stage * GAS + ar * GA_LDH + ac8) * 2,
                       A + (size_t)(m0 + ar) * lda + k0 + ac8);
            int br = ch >> 4, bc8 = (ch & 15) << 3; // B: 32 rows x 128 cols
            CP_ASYNC16(sB + (stage * GBS + br * GB_LDH + bc8) * 2,
                       B + (size_t)(k0 + br) * ldb + n0 + bc8);
        }
    };

    wmma::fragment<wmma::accumulator, 16, 16, 16, float> acc[4][4];
#pragma unroll
    for (int i = 0; i < 4; i++)
#pragma unroll
        for (int j = 0; j < 4; j++) wmma::fill_fragment(acc[i][j], 0.f);

#pragma unroll
    for (int s = 0; s < NSTAGE - 1; s++) {
        if (s < nk) issue(s, s);
        CP_COMMIT();
    }

    for (int kt = 0; kt < nk; kt++) {
        CP_WAIT(NSTAGE - 2);
        __syncthreads();

        int nx = kt + NSTAGE - 1;
        if (nx < nk) issue(nx, nx & (NSTAGE - 1));
        CP_COMMIT();

        const int buf = kt & (NSTAGE - 1);
        const __half* Ab = As + buf * GAS;
        const __half* Bb = Bs + buf * GBS;
#pragma unroll
        for (int ks = 0; ks < 2; ks++) {
            wmma::fragment<wmma::matrix_a, 16, 16, 16, __half, wmma::row_major> af[4];
#pragma unroll
            for (int fm = 0; fm < 4; fm++)
                wmma::load_matrix_sync(af[fm], Ab + (wm * 64 + fm * 16) * GA_LDH + ks * 16, GA_LDH);
#pragma unroll
            for (int fn = 0; fn < 4; fn++) {
                wmma::fragment<wmma::matrix_b, 16, 16, 16, __half, wmma::row_major> bf;
                wmma::load_matrix_sync(bf, Bb + (ks * 16) * GB_LDH + wn * 64 + fn * 16, GB_LDH);
#pragma unroll
                for (int fm = 0; fm < 4; fm++)
                    wmma::mma_sync(acc[fm][fn], af[fm], bf, acc[fm][fn]);
            }
        }
    }
    CP_WAIT(0);
    __syncthreads();

    // epilogue: per-warp fp32 scratch 16 rows x 72 floats (4608 B each, 4 warps)
    float* sw = (float*)dsmem + warp * (16 * 72);
#pragma unroll
    for (int fm = 0; fm < 4; fm++) {
#pragma unroll
        for (int fn = 0; fn < 4; fn++)
            wmma::store_matrix_sync(sw + fn * 16, acc[fm][fn], 72, wmma::mem_row_major);
        __syncwarp();
        const int rowbase = m0 + wm * 64 + fm * 16;
        const int colbase = n0 + wn * 64;
#pragma unroll
        for (int it = 0; it < 8; it++) {
            int idx = lane + it * 32;       // 0..255
            int r  = idx >> 4;              // 0..15
            int c4 = (idx & 15) << 2;       // 0..60
            float4 v = *(float4*)(sw + r * 72 + c4);
            int row = rowbase + r;
            int col = colbase + c4;
            float4 bv = *(const float4*)(bias + col);
            v.x += bv.x; v.y += bv.y; v.z += bv.z; v.w += bv.w;
            if (ACT == 1) {
                v.x = fmaxf(v.x, 0.f); v.y = fmaxf(v.y, 0.f);
                v.z = fmaxf(v.z, 0.f); v.w = fmaxf(v.w, 0.f);
            }
            if (ACT == 2) {
                const float* Rf = (const float*)Rv;
                float4 rv = *(const float4*)(Rf + (size_t)row * ldr + col);
                v.x += rv.x; v.y += rv.y; v.z += rv.z; v.w += rv.w;
            }
            if (ACT == 3) {
                const __half* Rh = (const __half*)Rv;
                float hs[4], ht[4];
                uint2 u1 = *(const uint2*)(Rh + (size_t)row * ldr + col);
                uint2 u2 = *(const uint2*)(Rh + (size_t)row * ldr + 512 + col);
                {
                    __half2* hh = (__half2*)&u1;
                    float2 t0 = __half22float2(hh[0]), t1 = __half22float2(hh[1]);
                    hs[0] = t0.x; hs[1] = t0.y; hs[2] = t1.x; hs[3] = t1.y;
                }
                {
                    __half2* hh = (__half2*)&u2;
                    float2 t0 = __half22float2(hh[0]), t1 = __half22float2(hh[1]);
                    ht[0] = t0.x; ht[1] = t0.y; ht[2] = t1.x; ht[3] = t1.y;
                }
                float zx = 1.f / (1.f + __expf(-v.x));
                float zy = 1.f / (1.f + __expf(-v.y));
                float zz = 1.f / (1.f + __expf(-v.z));
                float zw = 1.f / (1.f + __expf(-v.w));
                v.x = zx * hs[0] + (1.f - zx) * ht[0];
                v.y = zy * hs[1] + (1.f - zy) * ht[1];
                v.z = zz * hs[2] + (1.f - zz) * ht[2];
                v.w = zw * hs[3] + (1.f - zw) * ht[3];
            }
            if constexpr (sizeof(OutT) == 2) {
                *(uint2*)((__half*)C + (size_t)row * ldc + col) = f4_to_h4(v);
            } else {
                *(float4*)((float*)C + (size_t)row * ldc + col) = v;
            }
        }
        __syncwarp();
    }
}

// ---------------- spatial attention: wmma flash, O resident in fragments ----------------
#define SA_QS_OFF   0
#define SA_KS_OFF   18432
#define SA_VS_OFF   27648
#define SA_SC_OFF   36864
#define SA_PS_OFF   71680
#define SA_RS_OFF   90112
#define SA_SMEM     90624

__global__ void __launch_bounds__(256, 2) spatial_attn_wmma_k(const __half* __restrict__ P,
                                                              __half* __restrict__ HS)
{
    extern __shared__ __align__(16) char dsm[];
    __half* Qs = (__half*)(dsm + SA_QS_OFF);
    __half* Ks = (__half*)(dsm + SA_KS_OFF);
    __half* Vs = (__half*)(dsm + SA_VS_OFF);
    float*  Sc = (float*)(dsm + SA_SC_OFF);
    __half* Ps = (__half*)(dsm + SA_PS_OFF);
    float*  Rs = (float*)(dsm + SA_RS_OFF);

    const int tid  = threadIdx.x;
    const int w    = tid >> 5;
    const int lane = tid & 31;
    const int q0   = blockIdx.x * 128;
    const int h    = blockIdx.y;
    const int bt   = blockIdx.z;

    const __half* base = P + (size_t)bt * NN * C3;

    for (int idx = tid; idx < 1024; idx += 256) {
        int row = idx >> 3, c8 = (idx & 7) << 3;
        *(uint4*)(Qs + row * 72 + c8) =
            *(const uint4*)(base + (size_t)(q0 + row) * C3 + h * HD + c8);
    }
    __syncthreads();

    wmma::fragment<wmma::matrix_a, 16, 16, 16, __half, wmma::row_major> qf[4];
#pragma unroll
    for (int i = 0; i < 4; i++)
        wmma::load_matrix_sync(qf[i], Qs + (w * 16) * 72 + i * 16, 72);

    float* Sw  = Sc + w * 1088;
    __half* Pw = Ps + w * 1152;
    float* Rw  = Rs + w * 16;
    const int r  = lane >> 1;
    const int hf = lane & 1;
    const int g  = lane >> 2;

    wmma::fragment<wmma::accumulator, 16, 16, 16, float> of[4];
#pragma unroll
    for (int j = 0; j < 4; j++) wmma::fill_fragment(of[j], 0.f);

    float m = -1e30f, l = 0.f;

    for (int tile = 0; tile < 8; tile++) {
        __syncthreads();
        for (int idx = tid; idx < 512; idx += 256) {
            int row = idx >> 3, c8 = (idx & 7) << 3;
            const __half* rp = base + (size_t)(tile * 64 + row) * C3 + h * HD + c8;
            *(uint4*)(Ks + row * 72 + c8) = *(const uint4*)(rp + 512);
            *(uint4*)(Vs + row * 72 + c8) = *(const uint4*)(rp + 1024);
        }
        __syncthreads();

        wmma::fragment<wmma::accumulator, 16, 16, 16, float> sf[4];
#pragma unroll
        for (int j = 0; j < 4; j++) wmma::fill_fragment(sf[j], 0.f);
#pragma unroll
        for (int i = 0; i < 4; i++) {
#pragma unroll
            for (int j = 0; j < 4; j++) {
                wmma::fragment<wmma::matrix_b, 16, 16, 16, __half, wmma::col_major> bf;
                wmma::load_matrix_sync(bf, Ks + (j * 16) * 72 + i * 16, 72);
                wmma::mma_sync(sf[j], qf[i], bf, sf[j]);
            }
        }
#pragma unroll
        for (int j = 0; j < 4; j++)
            wmma::store_matrix_sync(Sw + j * 16, sf[j], 68, wmma::mem_row_major);
        __syncwarp();

        const float* srow = Sw + r * 68 + hf * 32;
        float mx = -1e30f;
#pragma unroll
        for (int j = 0; j < 32; j++) mx = fmaxf(mx, srow[j]);
        mx = fmaxf(mx, __shfl_xor_sync(0xffffffffu, mx, 1));
        float tm = mx * 0.125f;
        float nm = fmaxf(m, tm);
        float rf = __expf(m - nm);
        float ps = 0.f;
        __half* prow = Pw + r * 72 + hf * 32;
#pragma unroll
        for (int j = 0; j < 32; j += 2) {
            float p0 = __expf(srow[j] * 0.125f - nm);
            float p1 = __expf(srow[j + 1] * 0.125f - nm);
            ps += p0 + p1;
            *(__half2*)(prow + j) = __floats2half2_rn(p0, p1);
        }
        ps += __shfl_xor_sync(0xffffffffu, ps, 1);
        l = l * rf + ps;
        m = nm;
        if (hf == 0) Rw[r] = rf;
        __syncwarp();

        float r0 = Rw[g], r1 = Rw[g + 8];
#pragma unroll
        for (int j = 0; j < 4; j++)
#pragma unroll
            for (int e = 0; e < 8; e++)
                of[j].x[e] *= ((e >> 1) & 1) ? r1 : r0;

#pragma unroll
        for (int i = 0; i < 4; i++) {
            wmma::fragment<wmma::matrix_a, 16, 16, 16, __half, wmma::row_major> af;
            wmma::load_matrix_sync(af, Pw + i * 16, 72);
#pragma unroll
            for (int j = 0; j < 4; j++) {
                wmma::fragment<wmma::matrix_b, 16, 16, 16, __half, wmma::row_major> bf;
                wmma::load_matrix_sync(bf, Vs + (i * 16) * 72 + j * 16, 72);
                wmma::mma_sync(of[j], af, bf, of[j]);
            }
        }
        __syncwarp();
    }

#pragma unroll
    for (int j = 0; j < 4; j++)
        wmma::store_matrix_sync(Sw + j * 16, of[j], 68, wmma::mem_row_major);
    __syncwarp();
    float inv = 1.f / l;
    const float* orow = Sw + r * 68 + hf * 32;
    __half* op = HS + (size_t)(bt * NN + q0 + w * 16 + r) * 512 + h * HD + hf * 32;
#pragma unroll
    for (int i = 0; i < 8; i++) {
        float4 v = make_float4(orow[4 * i] * inv, orow[4 * i + 1] * inv,
                               orow[4 * i + 2] * inv, orow[4 * i + 3] * inv);
        *(uint2*)(op + i * 4) = f4_to_h4(v);
    }
}

// ---------------- temporal attention (causal over T=24, fp16 P) ----------------
__global__ void __launch_bounds__(192) temporal_attn_k(const __half* __restrict__ P,
                                                       __half* __restrict__ HT)
{
    const int n = blockIdx.x;
    const int b = blockIdx.y;
    const int h = threadIdx.x & 7;
    const int t = threadIdx.x >> 3;

    float q[64];
    {
        const uint4* qp = (const uint4*)(P + ((size_t)(b * TT + t) * NN + n) * C3 + 1536 + h * HD);
#pragma unroll
        for (int i = 0; i < 8; i++) h8_to_f8(__ldg(qp + i), q + 8 * i);
    }
    float o[64];
#pragma unroll
    for (int i = 0; i < 64; i++) o[i] = 0.f;
    float mr = -1e30f, l = 0.f;

    for (int s = 0; s <= t; s++) {
        size_t rk = ((size_t)(b * TT + s) * NN + n) * C3;
        const uint4* kp = (const uint4*)(P + rk + 2048 + h * HD);
        const uint4* vp = (const uint4*)(P + rk + 2560 + h * HD);
        float kb[64];
#pragma unroll
        for (int i = 0; i < 8; i++) h8_to_f8(__ldg(kp + i), kb + 8 * i);
        float s0 = 0.f, s1 = 0.f, s2 = 0.f, s3 = 0.f;
#pragma unroll
        for (int c = 0; c < 16; c++) {
            s0 += q[4 * c]     * kb[4 * c];
            s1 += q[4 * c + 1] * kb[4 * c + 1];
            s2 += q[4 * c + 2] * kb[4 * c + 2];
            s3 += q[4 * c + 3] * kb[4 * c + 3];
        }
        float sc = ((s0 + s1) + (s2 + s3)) * 0.125f;
        float vb[64];
#pragma unroll
        for (int i = 0; i < 8; i++) h8_to_f8(__ldg(vp + i), vb + 8 * i);
        if (sc <= mr) {
            float p = __expf(sc - mr);
            l += p;
#pragma unroll
            for (int c = 0; c < 64; c++) o[c] += p * vb[c];
        } else {
            float r = __expf(mr - sc);
            mr = sc;
            l = l * r + 1.f;
#pragma unroll
            for (int c = 0; c < 64; c++) o[c] = o[c] * r + vb[c];
        }
    }
    float inv = 1.f / l;
    __half* op = HT + ((size_t)(b * TT + t) * NN + n) * 512 + h * HD;
#pragma unroll
    for (int i = 0; i < 16; i++) {
        float4 v = make_float4(o[4 * i] * inv, o[4 * i + 1] * inv,
                               o[4 * i + 2] * inv, o[4 * i + 3] * inv);
        *(uint2*)(op + 4 * i) = f4_to_h4(v);
    }
}

// ---------------- launch ----------------
extern "C" void kernel_launch(void* const* d_in, const int* in_sizes, int n_in,
                              void* d_out, int out_size)
{
    const float* X    = (const float*)d_in[0];
    const float* STE  = (const float*)d_in[1];
    const float* sWq  = (const float*)d_in[2];
    const float* sbq  = (const float*)d_in[3];
    const float* sWk  = (const float*)d_in[4];
    const float* sbk  = (const float*)d_in[5];
    const float* sWv  = (const float*)d_in[6];
    const float* sbv  = (const float*)d_in[7];
    const float* sWo  = (const float*)d_in[8];
    const float* sbo  = (const float*)d_in[9];
    const float* tWq  = (const float*)d_in[10];
    const float* tbq  = (const float*)d_in[11];
    const float* tWk  = (const float*)d_in[12];
    const float* tbk  = (const float*)d_in[13];
    const float* tWv  = (const float*)d_in[14];
    const float* tbv  = (const float*)d_in[15];
    const float* tWo  = (const float*)d_in[16];
    const float* tbo  = (const float*)d_in[17];
    const float* gWxs = (const float*)d_in[18];
    const float* gWxt = (const float*)d_in[19];
    const float* gbxt = (const float*)d_in[20];
    const float* gWh1 = (const float*)d_in[21];
    const float* gbh1 = (const float*)d_in[22];
    const float* gWh2 = (const float*)d_in[23];
    const float* gbh2 = (const float*)d_in[24];
    float* out = (float*)d_out;

    __half *Xh, *Ph, *Wch, *Wgh, *sWoh, *tWoh, *Wh1h, *Wh2h, *HSh, *HTh, *HSTh;
    float *bcat;
    cudaGetSymbolAddress((void**)&Xh,   g_Xh);
    cudaGetSymbolAddress((void**)&Ph,   g_Ph);
    cudaGetSymbolAddress((void**)&Wch,  g_Wch);
    cudaGetSymbolAddress((void**)&bcat, g_bcat);
    cudaGetSymbolAddress((void**)&Wgh,  g_Wgh);
    cudaGetSymbolAddress((void**)&sWoh, g_sWoh);
    cudaGetSymbolAddress((void**)&tWoh, g_tWoh);
    cudaGetSymbolAddress((void**)&Wh1h, g_Wh1h);
    cudaGetSymbolAddress((void**)&Wh2h, g_Wh2h);
    cudaGetSymbolAddress((void**)&HSh,  g_HSh);
    cudaGetSymbolAddress((void**)&HTh,  g_HTh);
    cudaGetSymbolAddress((void**)&HSTh, g_HSTh);

    static int attr_set = 0;
    if (!attr_set) {
        cudaFuncSetAttribute(spatial_attn_wmma_k,
                             cudaFuncAttributeMaxDynamicSharedMemorySize, SA_SMEM);
        cudaFuncSetAttribute(gemm_cp_k<1, __half>,
                             cudaFuncAttributeMaxDynamicSharedMemorySize, GSMEM_DYN);
        cudaFuncSetAttribute(gemm_cp_k<3, __half>,
                             cudaFuncAttributeMaxDynamicSharedMemorySize, GSMEM_DYN);
        cudaFuncSetAttribute(gemm_cp_k<2, float>,
                             cudaFuncAttributeMaxDynamicSharedMemorySize, GSMEM_DYN);
        attr_set = 1;
    }

    // 1) fp16 conversions
    conv_xc_h<<<(MROWS * 384 + 255) / 256, 256>>>(X, STE, Xh);
    prep_weights_k<<<(PW_R4 + 255) / 256, 256>>>(
        sWq, sWk, sWv, tWq, tWk, tWv,
        sbq, sbk, sbv, tbq, tbk, tbv,
        gWxs, gWxt, sWo, tWo, gWh1, gWh2,
        Wch, Wgh, sWoh, tWoh, Wh1h, Wh2h, bcat);

    // 2) six projections in one GEMM: Ph = relu(Xh @ Wch + bcat)
    gemm_cp_k<1, __half><<<dim3(24, 192), 128, GSMEM_DYN>>>(
        Xh, Wch, bcat, nullptr, Ph, MROWS, 3072, 1536, 1536, 3072, 3072, 0);

    // 3) attention
    spatial_attn_wmma_k<<<dim3(4, NH, BB * TT), 256, SA_SMEM>>>(Ph, HSh);
    temporal_attn_k<<<dim3(NN, BB), 192>>>(Ph, HTh);

    // 4) output projections into HSTh = [relu(HS@sWo+b) | relu(HT@tWo+b)]
    gemm_cp_k<1, __half><<<dim3(4, 192), 128, GSMEM_DYN>>>(
        HSh, sWoh, sbo, nullptr, HSTh, MROWS, 512, 512, 512, 512, 1024, 0);
    gemm_cp_k<1, __half><<<dim3(4, 192), 128, GSMEM_DYN>>>(
        HTh, tWoh, tbo, nullptr, HSTh + 512, MROWS, 512, 512, 512, 512, 1024, 0);

    // 5) gated fusion fused in epilogue: H1 = sig(HST@Wg+b)*HSp + (1-sig)*HTp -> HSh
    gemm_cp_k<3, __half><<<dim3(4, 192), 128, GSMEM_DYN>>>(
        HSTh, Wgh, gbxt, HSTh, HSh, MROWS, 512, 1024, 1024, 512, 512, 1024);

    // 6) MLP: H2 = relu(H1 @ gWh1 + gbh1) -> HTh
    gemm_cp_k<1, __half><<<dim3(4, 192), 128, GSMEM_DYN>>>(
        HSh, Wh1h, gbh1, nullptr, HTh, MROWS, 512, 512, 512, 512, 512, 0);
    // out = X + H2 @ gWh2 + gbh2   (fp32 out)
    gemm_cp_k<2, float><<<dim3(4, 192), 128, GSMEM_DYN>>>(
        HTh, Wh2h, gbh2, X, out, MROWS, 512, 512, 512, 512, 512, 512);
}